// round 7
// baseline (speedup 1.0000x reference)
#include <cuda_runtime.h>
#include <cstdint>

#define BSZ      8
#define SEQ      16
#define DMODEL   512
#define MAXSEQ   8192
#define SPOS     4096
#define KVLEN    4112
#define NROWS    (BSZ*SEQ)        // 128
#define ATT_SCALE 0.0625f         // (512/2)^-0.5
#define NSPL     33               // kv splits of 128 (last has 16)

typedef unsigned long long u64;

__device__ __forceinline__ u64 ffma2(u64 a, u64 b, u64 c){
    u64 d; asm("fma.rn.f32x2 %0,%1,%2,%3;" : "=l"(d) : "l"(a), "l"(b), "l"(c)); return d;
}
__device__ __forceinline__ u64 bcast2(float x){
    u64 d; asm("mov.b64 %0,{%1,%1};" : "=l"(d) : "f"(x)); return d;
}
__device__ __forceinline__ float2 unpk(u64 v){
    float2 f; asm("mov.b64 {%0,%1},%2;" : "=f"(f.x), "=f"(f.y) : "l"(v)); return f;
}
__device__ __forceinline__ void cp16(uint32_t s, const void* g, int sz){
    asm volatile("cp.async.cg.shared.global [%0], [%1], 16, %2;" :: "r"(s), "l"(g), "r"(sz));
}
__device__ __forceinline__ void cpcommit(){ asm volatile("cp.async.commit_group;"); }
template<int N> __device__ __forceinline__ void cpwait(){ asm volatile("cp.async.wait_group %0;" :: "n"(N)); }

// ---- scratch ----
__device__ float g_qT[BSZ*DMODEL*SEQ];                 // [b][d][q]
__device__ float g_k[NROWS*DMODEL];
__device__ float g_v[NROWS*DMODEL];
__device__ float g_pacc[(size_t)BSZ*NSPL*SEQ*DMODEL];  // 8.65MB partial PV acc
__device__ float g_ml[BSZ*NSPL*SEQ*2];                 // per-split m,l

// ============================================================
// gemm body (16m x 128e, W [e][512] row-major), A already in smem
// ============================================================
__device__ __forceinline__ void gemm_from_smem(
    const float* __restrict__ Asm, float* __restrict__ Wsm,
    const float* __restrict__ W, int e0, u64 (&acc)[4][2])
{
    const int tid = threadIdx.x;
    const int tx = tid & 31, ty = tid >> 5;
    const float* wrow = W + (size_t)(e0 + tid)*DMODEL;

#pragma unroll
    for (int mi = 0; mi < 4; mi++){ acc[mi][0] = 0ull; acc[mi][1] = 0ull; }

    float4 st[8];
#pragma unroll
    for (int j = 0; j < 8; j++) st[j] = ((const float4*)wrow)[j];
#pragma unroll
    for (int j = 0; j < 8; j++){
        Wsm[(j*4+0)*128+tid] = st[j].x; Wsm[(j*4+1)*128+tid] = st[j].y;
        Wsm[(j*4+2)*128+tid] = st[j].z; Wsm[(j*4+3)*128+tid] = st[j].w;
    }
    __syncthreads();

    for (int t = 0; t < 16; t++){
        if (t < 15){
            const float4* src = (const float4*)(wrow + (t+1)*32);
#pragma unroll
            for (int j = 0; j < 8; j++) st[j] = src[j];
        }
        const int kb = t*32;
#pragma unroll
        for (int k = 0; k < 32; k++){
            ulonglong2 w = *(const ulonglong2*)&Wsm[k*128 + tx*4];
#pragma unroll
            for (int mi = 0; mi < 4; mi++){
                u64 av = bcast2(Asm[(ty*4+mi)*DMODEL + kb + k]);
                acc[mi][0] = ffma2(av, w.x, acc[mi][0]);
                acc[mi][1] = ffma2(av, w.y, acc[mi][1]);
            }
        }
        if (t < 15){
            __syncthreads();
#pragma unroll
            for (int j = 0; j < 8; j++){
                Wsm[(j*4+0)*128+tid] = st[j].x; Wsm[(j*4+1)*128+tid] = st[j].y;
                Wsm[(j*4+2)*128+tid] = st[j].z; Wsm[(j*4+3)*128+tid] = st[j].w;
            }
            __syncthreads();
        }
    }
}

// ---- fused QKV: z=0 -> Q transposed, z=1 -> K, z=2 -> V ----
__global__ void __launch_bounds__(128) qkv_kernel(
    const float* __restrict__ x,
    const float* __restrict__ Wq, const float* __restrict__ Wk, const float* __restrict__ Wv)
{
    __shared__ float Asm[16*DMODEL];
    __shared__ float Wsm[32*128];
    const int tid = threadIdx.x;
    const int tx = tid & 31, ty = tid >> 5;
    const int e0 = blockIdx.x * 128, b = blockIdx.y;
    const int z = blockIdx.z;
    const float* W = (z == 0) ? Wq : (z == 1) ? Wk : Wv;

    {
        const float4* src = (const float4*)(x + (size_t)b*SEQ*DMODEL);
        float4* dst = (float4*)Asm;
#pragma unroll
        for (int i = 0; i < 16; i++) dst[tid + i*128] = src[tid + i*128];
    }
    __syncthreads();

    u64 acc[4][2];
    gemm_from_smem(Asm, Wsm, W, e0, acc);

    if (z == 0){
        float* qT = g_qT + (size_t)b*DMODEL*SEQ;
#pragma unroll
        for (int mi = 0; mi < 4; mi++){
            float2 lo = unpk(acc[mi][0]), hi = unpk(acc[mi][1]);
            float v[4] = {lo.x, lo.y, hi.x, hi.y};
            int q = ty*4 + mi;
#pragma unroll
            for (int j = 0; j < 4; j++)
                qT[(size_t)(e0 + tx*4 + j)*SEQ + q] = v[j];
        }
    } else {
        float* C = (z == 1) ? g_k : g_v;
#pragma unroll
        for (int mi = 0; mi < 4; mi++){
            float2 lo = unpk(acc[mi][0]), hi = unpk(acc[mi][1]);
            float4 o = make_float4(lo.x, lo.y, hi.x, hi.y);
            *(float4*)&C[(size_t)(b*SEQ + ty*4 + mi)*DMODEL + e0 + tx*4] = o;
        }
    }
}

// ============================================================
// Fused attention: per (split, b): scores + weight write + local
// softmax + PV partial. Dynamic smem.
// ============================================================
#define OFF_AT   0                  // 8192 floats: Q^T [512][16]
#define OFF_WS   8192               // 2*128*20 = 5120: K chunks
#define OFF_VS   13312              // 2*8*516 = 8256: V chunks
#define OFF_SP   21568              // 16*132 = 2112: scores/probs
#define OFF_MS   23680              // 16
#define OFF_LS   23696              // 16
#define ATT_SMEM_BYTES (23712*4)

__global__ void __launch_bounds__(128) attn_kernel(
    const float* __restrict__ cache_k, const float* __restrict__ cache_v,
    const float* __restrict__ mask, float* __restrict__ weight)
{
    extern __shared__ float sm[];
    float* At = sm + OFF_AT;
    float* Ws = sm + OFF_WS;
    float* Vs = sm + OFF_VS;
    float* sP = sm + OFF_SP;
    float* mS = sm + OFF_MS;
    float* lS = sm + OFF_LS;

    const int tid = threadIdx.x;
    const int sp = blockIdx.x;
    const int b  = blockIdx.y;
    const int p0 = sp * 128;
    const int gp = p0 + tid;
    const bool pvalid = gp < KVLEN;

    uint32_t ws_base = (uint32_t)__cvta_generic_to_shared(Ws);
    uint32_t vs_base = (uint32_t)__cvta_generic_to_shared(Vs);
    const int lrow = tid >> 2, lcol = (tid & 3)*4;

    auto issueK = [&](int t){
        const int buf = t & 1;
#pragma unroll
        for (int j = 0; j < 4; j++){
            int row = lrow + j*32;
            int rp = p0 + row;
            const float* src;
            int sz = 16;
            if (rp < SPOS)       src = cache_k + ((size_t)b*MAXSEQ + rp)*DMODEL + t*16 + lcol;
            else if (rp < KVLEN) src = g_k + (size_t)(b*SEQ + rp - SPOS)*DMODEL + t*16 + lcol;
            else                 { src = cache_k; sz = 0; }
            uint32_t dst = ws_base + (uint32_t)(buf*2560 + row*20 + lcol)*4u;
            cp16(dst, src, sz);
        }
        cpcommit();
    };

    issueK(0);

    { // Q^T tile: 8192 contiguous floats
        const float4* src = (const float4*)(g_qT + (size_t)b*DMODEL*SEQ);
        float4* dst = (float4*)At;
#pragma unroll
        for (int i = 0; i < 16; i++) dst[tid + i*128] = src[tid + i*128];
    }

    // ---- phase 1: scores (thread owns one p, 16 q in f32x2 pairs) ----
    u64 s8[8];
#pragma unroll
    for (int i = 0; i < 8; i++) s8[i] = 0ull;

    for (int t = 0; t < 32; t++){
        if (t+1 < 32) issueK(t+1);
        if (t+1 < 32) cpwait<1>(); else cpwait<0>();
        __syncthreads();
        const float* wrow = Ws + (t&1)*2560 + tid*20;
#pragma unroll
        for (int kg = 0; kg < 4; kg++){
            float4 w4 = *(const float4*)&wrow[kg*4];
            float wv[4] = {w4.x, w4.y, w4.z, w4.w};
#pragma unroll
            for (int j = 0; j < 4; j++){
                const int kk = t*16 + kg*4 + j;
                u64 wp = bcast2(wv[j]);
                ulonglong2 a0 = *(const ulonglong2*)&At[kk*SEQ];
                ulonglong2 a1 = *(const ulonglong2*)&At[kk*SEQ + 4];
                ulonglong2 a2 = *(const ulonglong2*)&At[kk*SEQ + 8];
                ulonglong2 a3 = *(const ulonglong2*)&At[kk*SEQ + 12];
                s8[0] = ffma2(a0.x, wp, s8[0]);
                s8[1] = ffma2(a0.y, wp, s8[1]);
                s8[2] = ffma2(a1.x, wp, s8[2]);
                s8[3] = ffma2(a1.y, wp, s8[3]);
                s8[4] = ffma2(a2.x, wp, s8[4]);
                s8[5] = ffma2(a2.y, wp, s8[5]);
                s8[6] = ffma2(a3.x, wp, s8[6]);
                s8[7] = ffma2(a3.y, wp, s8[7]);
            }
        }
        __syncthreads();
    }

    float sv[16];
#pragma unroll
    for (int i = 0; i < 8; i++){
        float2 f = unpk(s8[i]);
        sv[2*i] = f.x; sv[2*i+1] = f.y;
    }

    if (pvalid){
#pragma unroll
        for (int q = 0; q < 16; q++){
            float w = sv[q]*ATT_SCALE;
            weight[(size_t)(b*SEQ + q)*KVLEN + gp] = w;
            sv[q] = w + mask[(size_t)q*KVLEN + gp];
        }
    } else {
#pragma unroll
        for (int q = 0; q < 16; q++) sv[q] = -1e30f;
    }
#pragma unroll
    for (int q = 0; q < 16; q++) sP[q*132 + tid] = sv[q];
    __syncthreads();

    // per-q max (warp w handles q = w*4..w*4+3)
    const int wrp = tid >> 5, lane = tid & 31;
#pragma unroll
    for (int j = 0; j < 4; j++){
        int q = wrp*4 + j;
        float v = fmaxf(fmaxf(sP[q*132+lane], sP[q*132+lane+32]),
                        fmaxf(sP[q*132+lane+64], sP[q*132+lane+96]));
#pragma unroll
        for (int off = 16; off > 0; off >>= 1)
            v = fmaxf(v, __shfl_xor_sync(0xffffffffu, v, off));
        if (lane == 0) mS[q] = v;
    }
    __syncthreads();

    // exp
#pragma unroll
    for (int q = 0; q < 16; q++)
        sP[q*132 + tid] = __expf(sv[q] - mS[q]);
    __syncthreads();

    // per-q sum
#pragma unroll
    for (int j = 0; j < 4; j++){
        int q = wrp*4 + j;
        float v = sP[q*132+lane] + sP[q*132+lane+32] + sP[q*132+lane+64] + sP[q*132+lane+96];
#pragma unroll
        for (int off = 16; off > 0; off >>= 1)
            v += __shfl_xor_sync(0xffffffffu, v, off);
        if (lane == 0) lS[q] = v;
    }
    __syncthreads();

    if (tid < 16){
        g_ml[((b*NSPL + sp)*SEQ + tid)*2 + 0] = mS[tid];
        g_ml[((b*NSPL + sp)*SEQ + tid)*2 + 1] = lS[tid];
    }

    // ---- phase 2: PV partial (thread: 4q x 16cols) ----
    auto issueV = [&](int t){
        const int buf = t & 1;
#pragma unroll
        for (int j = 0; j < 8; j++){
            int kv = p0 + t*8 + j;
            const float* src;
            int sz = 16;
            if (kv < SPOS)        src = cache_v + ((size_t)b*MAXSEQ + kv)*DMODEL + tid*4;
            else if (kv < KVLEN)  src = g_v + (size_t)(b*SEQ + kv - SPOS)*DMODEL + tid*4;
            else                  { src = cache_v; sz = 0; }
            uint32_t dst = vs_base + (uint32_t)(buf*4128 + j*516 + tid*4)*4u;
            cp16(dst, src, sz);
        }
        cpcommit();
    };

    u64 acc[4][4][2];
#pragma unroll
    for (int mi = 0; mi < 4; mi++)
#pragma unroll
        for (int vt = 0; vt < 4; vt++){ acc[mi][vt][0] = 0ull; acc[mi][vt][1] = 0ull; }

    const int tx = tid & 31, ty = tid >> 5;
    issueV(0);
    for (int t = 0; t < 16; t++){
        if (t+1 < 16) issueV(t+1);
        if (t+1 < 16) cpwait<1>(); else cpwait<0>();
        __syncthreads();
        const float* vb = Vs + (t&1)*4128;
#pragma unroll
        for (int pp = 0; pp < 8; pp++){
            const int ip = t*8 + pp;
            u64 av[4];
#pragma unroll
            for (int mi = 0; mi < 4; mi++) av[mi] = bcast2(sP[(ty*4+mi)*132 + ip]);
#pragma unroll
            for (int vt = 0; vt < 4; vt++){
                ulonglong2 w = *(const ulonglong2*)&vb[pp*516 + vt*128 + tx*4];
#pragma unroll
                for (int mi = 0; mi < 4; mi++){
                    acc[mi][vt][0] = ffma2(av[mi], w.x, acc[mi][vt][0]);
                    acc[mi][vt][1] = ffma2(av[mi], w.y, acc[mi][vt][1]);
                }
            }
        }
        __syncthreads();
    }

    float* dst = g_pacc + (size_t)(b*NSPL + sp)*SEQ*DMODEL;
#pragma unroll
    for (int mi = 0; mi < 4; mi++){
        const int q = ty*4 + mi;
#pragma unroll
        for (int vt = 0; vt < 4; vt++){
            float2 lo = unpk(acc[mi][vt][0]), hi = unpk(acc[mi][vt][1]);
            float4 o = make_float4(lo.x, lo.y, hi.x, hi.y);
            *(float4*)&dst[(size_t)q*DMODEL + vt*128 + tx*4] = o;
        }
    }
}

// ============================================================
// Wo projection with fused split-combine in A-tile build.
// Dynamic smem: Asm 8192 + Wsm 4096 + coef 528 = 12816 floats
// ============================================================
#define WO_SMEM_BYTES (12816*4)
__global__ void __launch_bounds__(128) gemm_wo(
    const float* __restrict__ W, float* __restrict__ out)
{
    extern __shared__ float sm[];
    float* Asm  = sm;
    float* Wsm  = sm + 8192;
    float* coef = sm + 12288;
    const int tid = threadIdx.x;
    const int tx = tid & 31, ty = tid >> 5;
    const int e0 = blockIdx.x * 128, b = blockIdx.y;

    if (tid < 16){
        const int q = tid;
        float M = -1e30f;
#pragma unroll
        for (int s = 0; s < NSPL; s++)
            M = fmaxf(M, g_ml[((b*NSPL + s)*SEQ + q)*2]);
        float denom = 0.f;
#pragma unroll
        for (int s = 0; s < NSPL; s++){
            float m = g_ml[((b*NSPL + s)*SEQ + q)*2];
            float l = g_ml[((b*NSPL + s)*SEQ + q)*2 + 1];
            float c = __expf(m - M);
            coef[s*16 + q] = c;
            denom += l * c;
        }
        float inv = 1.f/denom;
#pragma unroll
        for (int s = 0; s < NSPL; s++) coef[s*16 + q] *= inv;
    }
    __syncthreads();

    // build combined A tile: Asm[q][d] = sum_s pacc[b][s][q][d]*coef[s][q]
#pragma unroll 1
    for (int q = 0; q < 16; q++){
        float4 a = make_float4(0.f,0.f,0.f,0.f);
        const float* pbase = g_pacc + ((size_t)(b*NSPL)*SEQ + q)*DMODEL + tid*4;
#pragma unroll 1
        for (int s = 0; s < NSPL; s++){
            float c = coef[s*16 + q];
            float4 p = *(const float4*)(pbase + (size_t)s*SEQ*DMODEL);
            a.x += p.x*c; a.y += p.y*c; a.z += p.z*c; a.w += p.w*c;
        }
        *(float4*)&Asm[q*DMODEL + tid*4] = a;
    }
    __syncthreads();

    u64 acc[4][2];
    gemm_from_smem(Asm, Wsm, W, e0, acc);

#pragma unroll
    for (int mi = 0; mi < 4; mi++){
        float2 lo = unpk(acc[mi][0]), hi = unpk(acc[mi][1]);
        float4 o = make_float4(lo.x, lo.y, hi.x, hi.y);
        *(float4*)&out[(size_t)(b*SEQ + ty*4 + mi)*DMODEL + e0 + tx*4] = o;
    }
}

// ============================================================
extern "C" void kernel_launch(void* const* d_in, const int* in_sizes, int n_in,
                              void* d_out, int out_size)
{
    const float* x       = (const float*)d_in[0];
    const float* mask    = (const float*)d_in[2];
    const float* Wq      = (const float*)d_in[3];
    const float* Wk      = (const float*)d_in[4];
    const float* Wv      = (const float*)d_in[5];
    const float* Wo      = (const float*)d_in[6];
    const float* cache_k = (const float*)d_in[7];
    const float* cache_v = (const float*)d_in[8];

    float* out    = (float*)d_out;
    float* weight = out + (size_t)NROWS*DMODEL;

    cudaFuncSetAttribute(attn_kernel, cudaFuncAttributeMaxDynamicSharedMemorySize, ATT_SMEM_BYTES);
    cudaFuncSetAttribute(gemm_wo,     cudaFuncAttributeMaxDynamicSharedMemorySize, WO_SMEM_BYTES);

    qkv_kernel<<<dim3(4, 8, 3), 128>>>(x, Wq, Wk, Wv);
    attn_kernel<<<dim3(NSPL, 8), 128, ATT_SMEM_BYTES>>>(cache_k, cache_v, mask, weight);
    gemm_wo<<<dim3(4, 8), 128, WO_SMEM_BYTES>>>(Wo, out);
}

// round 12
// speedup vs baseline: 2.5191x; 2.5191x over previous
#include <cuda_runtime.h>
#include <cstdint>

#define BSZ      8
#define SEQ      16
#define DMODEL   512
#define MAXSEQ   8192
#define SPOS     4096
#define KVLEN    4112
#define NROWS    (BSZ*SEQ)        // 128
#define ATT_SCALE 0.0625f         // (512/2)^-0.5
#define NSPL     32               // pv splits of 128 (last has +16)
#define KHALF    256              // scores k-split
#define KCH      16
#define NCH      (KHALF/KCH)
#define PSTRIDE  4224             // 33*128

typedef unsigned long long u64;

__device__ __forceinline__ u64 ffma2(u64 a, u64 b, u64 c){
    u64 d; asm("fma.rn.f32x2 %0,%1,%2,%3;" : "=l"(d) : "l"(a), "l"(b), "l"(c)); return d;
}
__device__ __forceinline__ u64 bcast2(float x){
    u64 d; asm("mov.b64 %0,{%1,%1};" : "=l"(d) : "f"(x)); return d;
}
__device__ __forceinline__ float2 unpk(u64 v){
    float2 f; asm("mov.b64 {%0,%1},%2;" : "=f"(f.x), "=f"(f.y) : "l"(v)); return f;
}
__device__ __forceinline__ void cp16(uint32_t s, const void* g, int sz){
    asm volatile("cp.async.cg.shared.global [%0], [%1], 16, %2;" :: "r"(s), "l"(g), "r"(sz));
}
__device__ __forceinline__ void cpcommit(){ asm volatile("cp.async.commit_group;"); }
template<int N> __device__ __forceinline__ void cpwait(){ asm volatile("cp.async.wait_group %0;" :: "n"(N)); }

// ---- scratch ----
__device__ float g_qT[BSZ*DMODEL*SEQ];                 // [b][d][q]
__device__ float g_k[NROWS*DMODEL];
__device__ float g_v[NROWS*DMODEL];
__device__ float g_qkvp[12*NROWS*DMODEL];              // qkv split-K partials
__device__ float g_s1[(size_t)NROWS*PSTRIDE];
__device__ float g_s2[(size_t)NROWS*PSTRIDE];
__device__ float g_sc[(size_t)NROWS*PSTRIDE];          // probs
__device__ float g_part[(size_t)BSZ*NSPL*SEQ*DMODEL];  // pv partials 8MB
__device__ float g_att[NROWS*DMODEL];
__device__ float g_wop[4*NROWS*DMODEL];                // wo split-K partials

// ============================================================
// 128-K-chunk GEMM core: 16m x 128e partial, 4 substeps of 32k.
// Asm[16][128] already loaded. wrow = thread's W row chunk (128 floats).
// ============================================================
__device__ __forceinline__ void gemm128_core(
    const float* __restrict__ Asm, float* __restrict__ Wsm,
    const float* __restrict__ wrow, u64 (&acc)[4][2])
{
    const int tid = threadIdx.x;
    const int tx = tid & 31, ty = tid >> 5;

#pragma unroll
    for (int mi = 0; mi < 4; mi++){ acc[mi][0] = 0ull; acc[mi][1] = 0ull; }

    float4 st[8];
#pragma unroll
    for (int j = 0; j < 8; j++) st[j] = ((const float4*)wrow)[j];
#pragma unroll
    for (int j = 0; j < 8; j++){
        Wsm[(j*4+0)*128+tid] = st[j].x; Wsm[(j*4+1)*128+tid] = st[j].y;
        Wsm[(j*4+2)*128+tid] = st[j].z; Wsm[(j*4+3)*128+tid] = st[j].w;
    }
    __syncthreads();

    for (int t = 0; t < 4; t++){
        if (t < 3){
            const float4* src = (const float4*)(wrow + (t+1)*32);
#pragma unroll
            for (int j = 0; j < 8; j++) st[j] = src[j];
        }
        const int kb = t*32;
#pragma unroll
        for (int k = 0; k < 32; k++){
            ulonglong2 w = *(const ulonglong2*)&Wsm[k*128 + tx*4];
#pragma unroll
            for (int mi = 0; mi < 4; mi++){
                u64 av = bcast2(Asm[(ty*4+mi)*128 + kb + k]);
                acc[mi][0] = ffma2(av, w.x, acc[mi][0]);
                acc[mi][1] = ffma2(av, w.y, acc[mi][1]);
            }
        }
        if (t < 3){
            __syncthreads();
#pragma unroll
            for (int j = 0; j < 8; j++){
                Wsm[(j*4+0)*128+tid] = st[j].x; Wsm[(j*4+1)*128+tid] = st[j].y;
                Wsm[(j*4+2)*128+tid] = st[j].z; Wsm[(j*4+3)*128+tid] = st[j].w;
            }
            __syncthreads();
        }
    }
}

// ---- qkv split-K: grid (4 e-tiles, 8 b, 12 = z*4+ks) ----
__global__ void __launch_bounds__(128) qkv_split(
    const float* __restrict__ x,
    const float* __restrict__ Wq, const float* __restrict__ Wk, const float* __restrict__ Wv)
{
    __shared__ float Asm[16*128];
    __shared__ float Wsm[32*128];
    const int tid = threadIdx.x;
    const int tx = tid & 31, ty = tid >> 5;
    const int e0 = blockIdx.x*128, b = blockIdx.y;
    const int z = blockIdx.z >> 2, ks = blockIdx.z & 3;
    const int k0 = ks*128;
    const float* W = (z == 0) ? Wq : (z == 1) ? Wk : Wv;

#pragma unroll
    for (int j = 0; j < 4; j++){
        int fi = tid + j*128;
        int m = fi >> 5, c = (fi & 31)*4;
        *(float4*)&Asm[m*128 + c] = *(const float4*)&x[(size_t)(b*16+m)*DMODEL + k0 + c];
    }
    __syncthreads();

    u64 acc[4][2];
    gemm128_core(Asm, Wsm, W + (size_t)(e0+tid)*DMODEL + k0, acc);

    float* dst = g_qkvp + ((size_t)blockIdx.z*NROWS + b*16)*DMODEL;
#pragma unroll
    for (int mi = 0; mi < 4; mi++){
        float2 lo = unpk(acc[mi][0]), hi = unpk(acc[mi][1]);
        float4 o = make_float4(lo.x, lo.y, hi.x, hi.y);
        *(float4*)&dst[(size_t)(ty*4+mi)*DMODEL + e0 + tx*4] = o;
    }
}

// ---- qkv combine: 196608 elems ----
__global__ void __launch_bounds__(256) qkv_combine()
{
    int idx = blockIdx.x*256 + threadIdx.x;
    int z = idx >> 16;
    int rc = idx & 65535;
    int r = rc >> 9, c = rc & 511;
    float s = 0.f;
#pragma unroll
    for (int ks = 0; ks < 4; ks++)
        s += g_qkvp[((size_t)(z*4+ks)*NROWS + r)*DMODEL + c];
    if (z == 0){
        int b = r >> 4, q = r & 15;
        g_qT[((size_t)b*DMODEL + c)*SEQ + q] = s;
    } else if (z == 1) g_k[(size_t)r*DMODEL + c] = s;
    else               g_v[(size_t)r*DMODEL + c] = s;
}

// ============================================================
// scores (unchanged from R3): grid (33, 8, 2)
// ============================================================
__global__ void __launch_bounds__(128) scores_v3(const float* __restrict__ cache_k)
{
    __shared__ alignas(16) float At[KHALF*SEQ];
    __shared__ alignas(16) float Ws[2][128*(KCH+4)];
    const int tid = threadIdx.x;
    const int p0 = blockIdx.x * 128;
    const int b  = blockIdx.y;
    const int z  = blockIdx.z;
    const int koff = z * KHALF;
    float* s_out = (z == 0 ? g_s1 : g_s2) + (size_t)b*SEQ*PSTRIDE;

    {
        const float4* src = (const float4*)(g_qT + (size_t)b*DMODEL*SEQ + (size_t)koff*SEQ);
        float4* dst = (float4*)At;
#pragma unroll
        for (int i = 0; i < 8; i++) dst[tid + i*128] = src[tid + i*128];
    }

    uint32_t ws_base = (uint32_t)__cvta_generic_to_shared(&Ws[0][0]);
    const int lrow = tid >> 2;
    const int lcol = (tid & 3) * 4;

    auto issue = [&](int t){
        const int buf = t & 1;
#pragma unroll
        for (int j = 0; j < 4; j++){
            int row = lrow + j*32;
            int gp = p0 + row;
            const float* src;
            int sz = 16;
            if (gp < SPOS)       src = cache_k + ((size_t)b*MAXSEQ + gp)*DMODEL + koff + t*KCH + lcol;
            else if (gp < KVLEN) src = g_k + ((size_t)(b*SEQ + gp - SPOS))*DMODEL + koff + t*KCH + lcol;
            else                 { src = cache_k; sz = 0; }
            uint32_t dst = ws_base + (uint32_t)(buf*128*(KCH+4) + row*(KCH+4) + lcol)*4u;
            cp16(dst, src, sz);
        }
        cpcommit();
    };

    u64 acc[8];
#pragma unroll
    for (int i = 0; i < 8; i++) acc[i] = 0ull;

    issue(0);
    for (int t = 0; t < NCH; t++){
        if (t+1 < NCH) issue(t+1);
        if (t+1 < NCH) cpwait<1>(); else cpwait<0>();
        __syncthreads();
        const int buf = t & 1;
        const float* wrow = &Ws[buf][tid*(KCH+4)];
#pragma unroll
        for (int kg = 0; kg < KCH/4; kg++){
            float4 w4 = *(const float4*)&wrow[kg*4];
            float wv[4] = {w4.x, w4.y, w4.z, w4.w};
#pragma unroll
            for (int j = 0; j < 4; j++){
                const int kk = t*KCH + kg*4 + j;
                u64 wp = bcast2(wv[j]);
                ulonglong2 a0 = *(const ulonglong2*)&At[kk*SEQ];
                ulonglong2 a1 = *(const ulonglong2*)&At[kk*SEQ + 4];
                ulonglong2 a2 = *(const ulonglong2*)&At[kk*SEQ + 8];
                ulonglong2 a3 = *(const ulonglong2*)&At[kk*SEQ + 12];
                acc[0] = ffma2(a0.x, wp, acc[0]);
                acc[1] = ffma2(a0.y, wp, acc[1]);
                acc[2] = ffma2(a1.x, wp, acc[2]);
                acc[3] = ffma2(a1.y, wp, acc[3]);
                acc[4] = ffma2(a2.x, wp, acc[4]);
                acc[5] = ffma2(a2.y, wp, acc[5]);
                acc[6] = ffma2(a3.x, wp, acc[6]);
                acc[7] = ffma2(a3.y, wp, acc[7]);
            }
        }
        __syncthreads();
    }

    float* base = s_out + p0 + tid;
#pragma unroll
    for (int i = 0; i < 8; i++){
        float2 f = unpk(acc[i]);
        base[(size_t)(2*i)*PSTRIDE]   = f.x;
        base[(size_t)(2*i+1)*PSTRIDE] = f.y;
    }
}

// ============================================================
// softmax (unchanged from R3)
// ============================================================
__global__ void __launch_bounds__(256) softmax_v3(
    const float* __restrict__ mask, float* __restrict__ weight)
{
    const int row = blockIdx.x;
    const int q = row & 15;
    const int tid = threadIdx.x;
    const float4* s1 = (const float4*)(g_s1 + (size_t)row*PSTRIDE);
    const float4* s2 = (const float4*)(g_s2 + (size_t)row*PSTRIDE);
    const float4* mk = (const float4*)(mask + (size_t)q*KVLEN);
    float4* wout = (float4*)(weight + (size_t)row*KVLEN);
    float4* pout = (float4*)(g_sc + (size_t)row*PSTRIDE);
    const int N4 = KVLEN/4;

    __shared__ float red[256];
    float4 vals[5];
    float m = -1e30f;
#pragma unroll
    for (int j = 0; j < 5; j++){
        int i = tid + j*256;
        if (i < N4){
            float4 a = s1[i], c = s2[i], mm = mk[i];
            float4 w;
            w.x = (a.x+c.x)*ATT_SCALE; w.y = (a.y+c.y)*ATT_SCALE;
            w.z = (a.z+c.z)*ATT_SCALE; w.w = (a.w+c.w)*ATT_SCALE;
            wout[i] = w;
            float4 d = make_float4(w.x+mm.x, w.y+mm.y, w.z+mm.z, w.w+mm.w);
            vals[j] = d;
            m = fmaxf(m, fmaxf(fmaxf(d.x,d.y), fmaxf(d.z,d.w)));
        }
    }
    red[tid] = m; __syncthreads();
    for (int st = 128; st > 0; st >>= 1){
        if (tid < st) red[tid] = fmaxf(red[tid], red[tid+st]);
        __syncthreads();
    }
    m = red[0]; __syncthreads();

    float sum = 0.f;
#pragma unroll
    for (int j = 0; j < 5; j++){
        int i = tid + j*256;
        if (i < N4){
            float4 d = vals[j];
            float4 e = make_float4(__expf(d.x-m), __expf(d.y-m), __expf(d.z-m), __expf(d.w-m));
            vals[j] = e;
            sum += e.x + e.y + e.z + e.w;
        }
    }
    red[tid] = sum; __syncthreads();
    for (int st = 128; st > 0; st >>= 1){
        if (tid < st) red[tid] += red[tid+st];
        __syncthreads();
    }
    float inv = 1.f/red[0];
#pragma unroll
    for (int j = 0; j < 5; j++){
        int i = tid + j*256;
        if (i < N4){
            float4 e = vals[j];
            pout[i] = make_float4(e.x*inv, e.y*inv, e.z*inv, e.w*inv);
        }
    }
}

// ============================================================
// pv_v4: one block per (split, b), full 512 cols, micro 4q x 16c.
// grid (32, 8), 128 threads. dyn smem.
// ============================================================
#define PV_PSTR  148
#define PV_VSTR  516
#define PV_SMEM  ((16*PV_PSTR + 2*16*PV_VSTR)*4)   // 75,520 B

__global__ void __launch_bounds__(128) pv_v4(const float* __restrict__ cache_v)
{
    extern __shared__ float sm[];
    float* Ps = sm;                     // [16][PV_PSTR]
    float* Vs = sm + 16*PV_PSTR;        // [2][16][PV_VSTR]
    const int tid = threadIdx.x;
    const int tx = tid & 31, ty = tid >> 5;
    const int sp = blockIdx.x, b = blockIdx.y;
    const int kv0 = sp*128;
    const int T = (sp == NSPL-1) ? 9 : 8;

    // load probs for this split: 16 q rows x 144 cols (g_sc padded to 4224)
    for (int i = tid; i < 16*36; i += 128){
        int q = i / 36, c4 = i % 36;
        float4 p = *(const float4*)&g_sc[(size_t)(b*SEQ + q)*PSTRIDE + kv0 + c4*4];
        *(float4*)&Ps[q*PV_PSTR + c4*4] = p;
    }

    uint32_t vs_base = (uint32_t)__cvta_generic_to_shared(Vs);
    auto issueV = [&](int t){
        const int buf = t & 1;
#pragma unroll
        for (int j = 0; j < 16; j++){
            int fi = tid + j*128;
            int row = fi >> 7, c = (fi & 127)*4;
            int kv = kv0 + t*16 + row;
            const float* src;
            int sz = 16;
            if (kv < SPOS)        src = cache_v + ((size_t)b*MAXSEQ + kv)*DMODEL + c;
            else if (kv < KVLEN)  src = g_v + (size_t)(b*SEQ + kv - SPOS)*DMODEL + c;
            else                  { src = cache_v; sz = 0; }
            uint32_t dst = vs_base + (uint32_t)(buf*16*PV_VSTR + row*PV_VSTR + c)*4u;
            cp16(dst, src, sz);
        }
        cpcommit();
    };

    u64 acc[4][4][2];
#pragma unroll
    for (int mi = 0; mi < 4; mi++)
#pragma unroll
        for (int vt = 0; vt < 4; vt++){ acc[mi][vt][0] = 0ull; acc[mi][vt][1] = 0ull; }

    issueV(0);
    __syncthreads();   // Ps visible
    for (int t = 0; t < T; t++){
        if (t+1 < T) issueV(t+1);
        if (t+1 < T) cpwait<1>(); else cpwait<0>();
        __syncthreads();
        const float* vb = Vs + (t&1)*16*PV_VSTR;
#pragma unroll
        for (int pp = 0; pp < 16; pp++){
            const int ip = t*16 + pp;
            u64 av[4];
#pragma unroll
            for (int mi = 0; mi < 4; mi++) av[mi] = bcast2(Ps[(ty*4+mi)*PV_PSTR + ip]);
#pragma unroll
            for (int vt = 0; vt < 4; vt++){
                ulonglong2 w = *(const ulonglong2*)&vb[pp*PV_VSTR + vt*128 + tx*4];
#pragma unroll
                for (int mi = 0; mi < 4; mi++){
                    acc[mi][vt][0] = ffma2(av[mi], w.x, acc[mi][vt][0]);
                    acc[mi][vt][1] = ffma2(av[mi], w.y, acc[mi][vt][1]);
                }
            }
        }
        __syncthreads();
    }

    float* dst = g_part + (size_t)(b*NSPL + sp)*SEQ*DMODEL;
#pragma unroll
    for (int mi = 0; mi < 4; mi++){
        const int q = ty*4 + mi;
#pragma unroll
        for (int vt = 0; vt < 4; vt++){
            float2 lo = unpk(acc[mi][vt][0]), hi = unpk(acc[mi][vt][1]);
            float4 o = make_float4(lo.x, lo.y, hi.x, hi.y);
            *(float4*)&dst[(size_t)q*DMODEL + vt*128 + tx*4] = o;
        }
    }
}

// ---- reduce pv partials -> g_att ----
__global__ void __launch_bounds__(256) reduce_kernel()
{
    int i = blockIdx.x*256 + threadIdx.x;
    int r = i >> 9, c = i & 511;
    int b = r >> 4, q = r & 15;
    float sum = 0.f;
#pragma unroll
    for (int s = 0; s < NSPL; s++)
        sum += g_part[(size_t)((b*NSPL + s)*SEQ + q)*DMODEL + c];
    g_att[(size_t)r*DMODEL + c] = sum;
}

// ---- Wo split-K: grid (4 e-tiles, 8 b, 4 ks) ----
__global__ void __launch_bounds__(128) wo_split(const float* __restrict__ Wo)
{
    __shared__ float Asm[16*128];
    __shared__ float Wsm[32*128];
    const int tid = threadIdx.x;
    const int tx = tid & 31, ty = tid >> 5;
    const int e0 = blockIdx.x*128, b = blockIdx.y;
    const int ks = blockIdx.z;
    const int k0 = ks*128;

#pragma unroll
    for (int j = 0; j < 4; j++){
        int fi = tid + j*128;
        int m = fi >> 5, c = (fi & 31)*4;
        *(float4*)&Asm[m*128 + c] = *(const float4*)&g_att[(size_t)(b*16+m)*DMODEL + k0 + c];
    }
    __syncthreads();

    u64 acc[4][2];
    gemm128_core(Asm, Wsm, Wo + (size_t)(e0+tid)*DMODEL + k0, acc);

    float* dst = g_wop + ((size_t)ks*NROWS + b*16)*DMODEL;
#pragma unroll
    for (int mi = 0; mi < 4; mi++){
        float2 lo = unpk(acc[mi][0]), hi = unpk(acc[mi][1]);
        float4 o = make_float4(lo.x, lo.y, hi.x, hi.y);
        *(float4*)&dst[(size_t)(ty*4+mi)*DMODEL + e0 + tx*4] = o;
    }
}

// ---- Wo combine -> out ----
__global__ void __launch_bounds__(256) wo_combine(float* __restrict__ out)
{
    int i = blockIdx.x*256 + threadIdx.x;
    float s = 0.f;
#pragma unroll
    for (int ks = 0; ks < 4; ks++)
        s += g_wop[(size_t)ks*NROWS*DMODEL + i];
    out[i] = s;
}

// ============================================================
extern "C" void kernel_launch(void* const* d_in, const int* in_sizes, int n_in,
                              void* d_out, int out_size)
{
    const float* x       = (const float*)d_in[0];
    const float* mask    = (const float*)d_in[2];
    const float* Wq      = (const float*)d_in[3];
    const float* Wk      = (const float*)d_in[4];
    const float* Wv      = (const float*)d_in[5];
    const float* Wo      = (const float*)d_in[6];
    const float* cache_k = (const float*)d_in[7];
    const float* cache_v = (const float*)d_in[8];

    float* out    = (float*)d_out;
    float* weight = out + (size_t)NROWS*DMODEL;

    cudaFuncSetAttribute(pv_v4, cudaFuncAttributeMaxDynamicSharedMemorySize, PV_SMEM);

    qkv_split<<<dim3(4, 8, 12), 128>>>(x, Wq, Wk, Wv);
    qkv_combine<<<768, 256>>>();
    scores_v3<<<dim3(33, 8, 2), 128>>>(cache_k);
    softmax_v3<<<NROWS, 256>>>(mask, weight);
    pv_v4<<<dim3(NSPL, 8), 128, PV_SMEM>>>(cache_v);
    reduce_kernel<<<256, 256>>>();
    wo_split<<<dim3(4, 8, 4), 128>>>(Wo);
    wo_combine<<<256, 256>>>(out);
}